// round 10
// baseline (speedup 1.0000x reference)
#include <cuda_runtime.h>
#include <cuda_fp16.h>
#include <cstdint>

#define C 64
#define D 512
#define TEMP_INV 10.0f
#define GLW 0.5f
#define NHB 128            // histogram/scatter blocks
#define NSEG 8             // segments per class in gather

// ---------------- device globals (scratch; no allocation allowed) ----------------
__device__ int    g_hist_part[NHB * C];     // per-block label histograms
__device__ int    g_base[NHB * C];          // per-block scatter bases
__device__ int    g_count[C];
__device__ int    g_off[C];
__device__ float  g_scale[C];               // TEMP_INV / count
__device__ int    g_rows[65536];            // row indices sorted by label
__device__ float  g_part[C * NSEG * D];     // per-(class,seg) partial sums (overwritten)
__device__ __half g_cent[C * D];            // fp16 centroids, TEMP/count folded
__device__ float  g_loss[2];
__device__ int    g_done;                   // zero-init at load; reset each run

// ---------------- K0: per-block label histogram ----------------
__global__ void k_hist(const int* __restrict__ labels, int n) {
    __shared__ int h[C];
    int b = blockIdx.x, t = threadIdx.x;
    if (t < C) h[t] = 0;
    __syncthreads();
    int per = n / NHB;                       // 512
    for (int i = t; i < per; i += blockDim.x)
        atomicAdd(&h[labels[b * per + i]], 1);
    __syncthreads();
    if (t < C) g_hist_part[b * C + t] = h[t];
}

// ---------------- K1: counts, offsets, per-block bases, scales (1 block) ----------------
__global__ void k_scan() {
    __shared__ int cnt_sh[C];
    int c = threadIdx.x;                     // 64 threads
    int total = 0;
#pragma unroll 8
    for (int b = 0; b < NHB; b++) total += g_hist_part[b * C + c];
    cnt_sh[c] = total;
    __syncthreads();
    int off = 0;
    for (int i = 0; i < c; i++) off += cnt_sh[i];
    g_count[c] = total;
    g_off[c] = off;
    g_scale[c] = TEMP_INV / (float)total;
    int running = off;
    for (int b = 0; b < NHB; b++) {
        g_base[b * C + c] = running;
        running += g_hist_part[b * C + c];
    }
    if (c < 2) g_loss[c] = 0.f;
}

// ---------------- K2: scatter row indices into label-sorted order ----------------
__global__ void k_scatter(const int* __restrict__ labels, int n) {
    __shared__ int cur[C];
    int b = blockIdx.x, t = threadIdx.x;
    if (t < C) cur[t] = g_base[b * C + t];
    __syncthreads();
    int per = n / NHB;                       // 512
    for (int i = t; i < per; i += blockDim.x) {
        int row = b * per + i;
        int lab = labels[row];
        int pos = atomicAdd(&cur[lab], 1);
        g_rows[pos] = row;
    }
}

// ---------------- K3: register-accumulation gather (no smem scatter) ----------------
// grid = C*NSEG = 512 blocks, 512 threads; thread t owns column t; ~4 CTAs/SM.
__global__ __launch_bounds__(512)
void k_gather(const float* __restrict__ S1) {
    int c = blockIdx.x >> 3, seg = blockIdx.x & (NSEG - 1);
    int cnt = g_count[c], off = g_off[c];
    int s0 = off + (cnt * seg) / NSEG;
    int s1 = off + (cnt * (seg + 1)) / NSEG;
    int t = threadIdx.x;
    float acc = 0.f;
    int i = s0;
    for (; i + 8 <= s1; i += 8) {
        // front-batched independent loads (row idx broadcast, values coalesced)
        int r0 = g_rows[i + 0], r1 = g_rows[i + 1], r2 = g_rows[i + 2], r3 = g_rows[i + 3];
        int r4 = g_rows[i + 4], r5 = g_rows[i + 5], r6 = g_rows[i + 6], r7 = g_rows[i + 7];
        float v0 = S1[(size_t)r0 * D + t];
        float v1 = S1[(size_t)r1 * D + t];
        float v2 = S1[(size_t)r2 * D + t];
        float v3 = S1[(size_t)r3 * D + t];
        float v4 = S1[(size_t)r4 * D + t];
        float v5 = S1[(size_t)r5 * D + t];
        float v6 = S1[(size_t)r6 * D + t];
        float v7 = S1[(size_t)r7 * D + t];
        acc += v0; acc += v1; acc += v2; acc += v3;
        acc += v4; acc += v5; acc += v6; acc += v7;
    }
    for (; i < s1; i++) acc += S1[(size_t)g_rows[i] * D + t];
    g_part[blockIdx.x * D + t] = acc;
}

// ---------------- K4: reduce segment partials -> fp16 centroids ----------------
__global__ void k_conv() {
    int c = blockIdx.x, t = threadIdx.x;     // 64 blocks x 512 threads
    float s = 0.f;
#pragma unroll
    for (int seg = 0; seg < NSEG; seg++) s += g_part[(c * NSEG + seg) * D + t];
    g_cent[c * D + t] = __float2half(s * g_scale[c]);
}

// ---------------- K5: staging + interleaved dual GEMM + weighted CE + finalize -------
__device__ __forceinline__ uint32_t f2h2(const float* p) {
    float2 f = *reinterpret_cast<const float2*>(p);
    __half2 h = __float22half2_rn(f);
    return *reinterpret_cast<uint32_t*>(&h);
}

__device__ __forceinline__ void mma16816(float* c,
                                         uint32_t a0, uint32_t a1, uint32_t a2, uint32_t a3,
                                         uint32_t b0, uint32_t b1) {
    asm volatile(
        "mma.sync.aligned.m16n8k16.row.col.f32.f16.f16.f32 "
        "{%0,%1,%2,%3}, {%4,%5,%6,%7}, {%8,%9}, {%0,%1,%2,%3};\n"
        : "+f"(c[0]), "+f"(c[1]), "+f"(c[2]), "+f"(c[3])
        : "r"(a0), "r"(a1), "r"(a2), "r"(a3), "r"(b0), "r"(b1));
}

#define P2_THREADS 256
#define P2_BLOCKS 296
#define CENT_STRIDE_H2 260   // (512+8)/2 half2 per class row -> conflict-free B loads
#define CENT_SMEM_BYTES (C * 520 * 2)

__global__ __launch_bounds__(P2_THREADS, 2)
void k_main(const float* __restrict__ S1, const float* __restrict__ S2,
            const int* __restrict__ labels, const float* __restrict__ sim,
            float* __restrict__ out, int n) {
    extern __shared__ __half cent_sh[];
    __shared__ float red[8][2];

    int tid = threadIdx.x;

    // Stage fp16 centroids into padded shared: 4096 uint4 (8 halfs each)
    {
        const uint4* src = reinterpret_cast<const uint4*>(g_cent);
        for (int i = tid; i < C * D / 8; i += P2_THREADS) {
            int c = i >> 6;                 // 64 uint4 per class row
            int x8 = i & 63;                // which 8-half chunk
            *reinterpret_cast<uint4*>(cent_sh + c * 520 + x8 * 8) = src[i];
        }
    }
    __syncthreads();

    const __half2* centh2 = reinterpret_cast<const __half2*>(cent_sh);
    int lane = tid & 31, wid = tid >> 5;
    int g = lane >> 2, t = lane & 3;
    int gwarp = blockIdx.x * (P2_THREADS / 32) + wid;
    int nwarps = gridDim.x * (P2_THREADS / 32);
    int ntiles = n >> 4;

    float lsum0 = 0.f, lsum1 = 0.f;

    for (int tile = gwarp; tile < ntiles; tile += nwarps) {
        int rb = tile << 4;

        // Hoisted: labels + sim weights load BEFORE the MMA loop (overlap latency)
        int lab0 = labels[rb + g];
        int lab1 = labels[rb + 8 + g];
        float4 wv0 = *reinterpret_cast<const float4*>(sim + (size_t)(rb + g) * 16 + t * 4);
        float4 wv1 = *reinterpret_cast<const float4*>(sim + (size_t)(rb + 8 + g) * 16 + t * 4);

        const float* a1r1 = S1 + (size_t)(rb + g) * D;
        const float* a1r2 = a1r1 + 8 * D;
        const float* a2r1 = S2 + (size_t)(rb + g) * D;
        const float* a2r2 = a2r1 + 8 * D;

        float acc[2][8][4];
#pragma unroll
        for (int m = 0; m < 2; m++)
#pragma unroll
            for (int nt = 0; nt < 8; nt++)
#pragma unroll
                for (int j = 0; j < 4; j++) acc[m][nt][j] = 0.f;

#pragma unroll 8
        for (int kt = 0; kt < D / 16; kt++) {
            int k0 = kt * 16 + t * 2;
            uint32_t a0m0 = f2h2(a1r1 + k0);
            uint32_t a1m0 = f2h2(a1r2 + k0);
            uint32_t a2m0 = f2h2(a1r1 + k0 + 8);
            uint32_t a3m0 = f2h2(a1r2 + k0 + 8);
            uint32_t a0m1 = f2h2(a2r1 + k0);
            uint32_t a1m1 = f2h2(a2r2 + k0);
            uint32_t a2m1 = f2h2(a2r1 + k0 + 8);
            uint32_t a3m1 = f2h2(a2r2 + k0 + 8);
#pragma unroll
            for (int nt = 0; nt < 8; nt++) {
                const __half2* bp = centh2 + (nt * 8 + g) * CENT_STRIDE_H2 + (k0 >> 1);
                uint32_t b0 = *reinterpret_cast<const uint32_t*>(bp);
                uint32_t b1 = *reinterpret_cast<const uint32_t*>(bp + 4);
                mma16816(acc[0][nt], a0m0, a1m0, a2m0, a3m0, b0, b1);
                mma16816(acc[1][nt], a0m1, a1m1, a2m1, a3m1, b0, b1);
            }
        }

        float w0 = wv0.x + wv0.y + wv0.z + wv0.w;
        float w1 = wv1.x + wv1.y + wv1.z + wv1.w;
        w0 += __shfl_xor_sync(0xffffffffu, w0, 1);
        w0 += __shfl_xor_sync(0xffffffffu, w0, 2);
        w1 += __shfl_xor_sync(0xffffffffu, w1, 1);
        w1 += __shfl_xor_sync(0xffffffffu, w1, 2);
        w0 *= (1.f / 16.f);
        w1 *= (1.f / 16.f);

#pragma unroll
        for (int m = 0; m < 2; m++) {
#pragma unroll
            for (int j = 0; j < 2; j++) {
                int lab = j ? lab1 : lab0;
                float w = j ? w1 : w0;
                float mx = -1e30f;
#pragma unroll
                for (int nt = 0; nt < 8; nt++) {
                    mx = fmaxf(mx, acc[m][nt][2 * j]);
                    mx = fmaxf(mx, acc[m][nt][2 * j + 1]);
                }
                mx = fmaxf(mx, __shfl_xor_sync(0xffffffffu, mx, 1));
                mx = fmaxf(mx, __shfl_xor_sync(0xffffffffu, mx, 2));
                float s = 0.f;
#pragma unroll
                for (int nt = 0; nt < 8; nt++) {
                    s += __expf(acc[m][nt][2 * j] - mx);
                    s += __expf(acc[m][nt][2 * j + 1] - mx);
                }
                s += __shfl_xor_sync(0xffffffffu, s, 1);
                s += __shfl_xor_sync(0xffffffffu, s, 2);
                float lse = mx + __logf(s);
                int nt_l = lab >> 3;
                int t_l = (lab >> 1) & 3;
                float sel = 0.f;
#pragma unroll
                for (int nt = 0; nt < 8; nt++) {
                    float v = (lab & 1) ? acc[m][nt][2 * j + 1] : acc[m][nt][2 * j];
                    sel += ((nt == nt_l) && (t == t_l)) ? v : 0.f;
                }
                sel += __shfl_xor_sync(0xffffffffu, sel, 1);
                sel += __shfl_xor_sync(0xffffffffu, sel, 2);
                float ce = (lse - sel) * w;   // quad-uniform
                if (m == 0) lsum0 += ce;
                else        lsum1 += ce;
            }
        }
    }

    // CE accumulated on all 4 quad lanes -> scale by 1/4
    lsum0 *= 0.25f;
    lsum1 *= 0.25f;
#pragma unroll
    for (int off = 16; off > 0; off >>= 1) {
        lsum0 += __shfl_down_sync(0xffffffffu, lsum0, off);
        lsum1 += __shfl_down_sync(0xffffffffu, lsum1, off);
    }
    if (lane == 0) { red[wid][0] = lsum0; red[wid][1] = lsum1; }
    __syncthreads();
    if (tid == 0) {
        float s0 = 0.f, s1 = 0.f;
#pragma unroll
        for (int wq = 0; wq < P2_THREADS / 32; wq++) { s0 += red[wq][0]; s1 += red[wq][1]; }
        atomicAdd(&g_loss[0], s0);
        atomicAdd(&g_loss[1], s1);
        __threadfence();
        int ticket = atomicAdd(&g_done, 1);
        if (ticket == gridDim.x - 1) {
            float L = g_loss[0] / (float)n;
            float G = g_loss[1] / (float)n;
            out[0] = 0.5f * ((1.f - GLW) * L + GLW * G);
            atomicExch(&g_done, 0);   // reset for next graph replay
        }
    }
}

// ---------------- launch ----------------
extern "C" void kernel_launch(void* const* d_in, const int* in_sizes, int n_in,
                              void* d_out, int out_size) {
    const float* S1 = (const float*)d_in[0];
    const float* S2 = (const float*)d_in[1];
    const int* seg = (const int*)d_in[2];
    const float* sim = (const float*)d_in[3];
    int n = in_sizes[2];  // N = 65536

    cudaFuncSetAttribute(k_main, cudaFuncAttributeMaxDynamicSharedMemorySize,
                         CENT_SMEM_BYTES);

    k_hist<<<NHB, 256>>>(seg, n);
    k_scan<<<1, C>>>();
    k_scatter<<<NHB, 256>>>(seg, n);
    k_gather<<<C * NSEG, 512>>>(S1);
    k_conv<<<C, 512>>>();
    k_main<<<P2_BLOCKS, P2_THREADS, CENT_SMEM_BYTES>>>(S1, S2, seg, sim, (float*)d_out, n);
}

// round 11
// speedup vs baseline: 1.5052x; 1.5052x over previous
#include <cuda_runtime.h>
#include <cuda_fp16.h>
#include <cstdint>

#define C 64
#define D 512
#define TEMP_INV 10.0f
#define GLW 0.5f
#define NHB 128            // histogram/scatter blocks
#define GSEG 32            // segments per class in gather

// ---------------- device globals (scratch; no allocation allowed) ----------------
__device__ int    g_hist_part[NHB * C];     // per-block label histograms
__device__ int    g_base[NHB * C];          // per-block scatter bases
__device__ int    g_count[C];
__device__ int    g_off[C];
__device__ float  g_scale[C];               // TEMP_INV / count
__device__ float  g_w[65536];               // per-row CE weight (sim mean)
__device__ int    g_rows[65536];            // row indices sorted by label
__device__ float  g_part[C * GSEG * D];     // per-(class,seg) partial sums (overwritten)
__device__ __half g_cent[C * D];            // fp16 centroids, TEMP/count folded
__device__ float  g_loss[2];
__device__ int    g_done;                   // zero-init at load; reset each run

// ---------------- K0: per-block label histogram + sim-mean weights ----------------
__global__ void k_pre(const int* __restrict__ labels, const float* __restrict__ sim, int n) {
    __shared__ int h[C];
    int b = blockIdx.x, t = threadIdx.x;
    if (t < C) h[t] = 0;
    __syncthreads();
    int per = n / NHB;                       // 512
    for (int i = t; i < per; i += blockDim.x)
        atomicAdd(&h[labels[b * per + i]], 1);
    // w = mean over 16 sim values; 2 rows per thread
    for (int i = t; i < per; i += blockDim.x) {
        int row = b * per + i;
        const float4* p = reinterpret_cast<const float4*>(sim + (size_t)row * 16);
        float4 v0 = p[0], v1 = p[1], v2 = p[2], v3 = p[3];
        float s = v0.x + v0.y + v0.z + v0.w + v1.x + v1.y + v1.z + v1.w
                + v2.x + v2.y + v2.z + v2.w + v3.x + v3.y + v3.z + v3.w;
        g_w[row] = s * (1.f / 16.f);
    }
    __syncthreads();
    if (t < C) g_hist_part[b * C + t] = h[t];
}

// ---------------- K1: counts, offsets, per-block bases, scales (1 block) ----------------
__global__ void k_scan() {
    __shared__ int cnt_sh[C];
    int c = threadIdx.x;                     // 64 threads
    int total = 0;
#pragma unroll 8
    for (int b = 0; b < NHB; b++) total += g_hist_part[b * C + c];
    cnt_sh[c] = total;
    __syncthreads();
    int off = 0;
    for (int i = 0; i < c; i++) off += cnt_sh[i];
    g_count[c] = total;
    g_off[c] = off;
    g_scale[c] = TEMP_INV / (float)total;
    int running = off;
    for (int b = 0; b < NHB; b++) {
        g_base[b * C + c] = running;
        running += g_hist_part[b * C + c];
    }
    if (c < 2) g_loss[c] = 0.f;
}

// ---------------- K2: scatter row indices into label-sorted order ----------------
__global__ void k_scatter(const int* __restrict__ labels, int n) {
    __shared__ int cur[C];
    int b = blockIdx.x, t = threadIdx.x;
    if (t < C) cur[t] = g_base[b * C + t];
    __syncthreads();
    int per = n / NHB;                       // 512
    for (int i = t; i < per; i += blockDim.x) {
        int row = b * per + i;
        int lab = labels[row];
        int pos = atomicAdd(&cur[lab], 1);
        g_rows[pos] = row;
    }
}

// ---------------- K3: register-accumulation gather, float4 columns ----------------
// grid = C*GSEG = 2048 blocks, 128 threads; lane q owns float4 column q (whole row = 2KB).
__global__ __launch_bounds__(128)
void k_gather(const float* __restrict__ S1) {
    int c = blockIdx.x >> 5, seg = blockIdx.x & (GSEG - 1);
    int cnt = g_count[c], off = g_off[c];
    int s0 = off + (cnt * seg) / GSEG;
    int s1 = off + (cnt * (seg + 1)) / GSEG;
    int q = threadIdx.x;                     // float4 column index 0..127
    const float4* Sv = reinterpret_cast<const float4*>(S1);
    float4 acc = make_float4(0.f, 0.f, 0.f, 0.f);
    int i = s0;
    for (; i + 4 <= s1; i += 4) {
        int r0 = g_rows[i + 0], r1 = g_rows[i + 1], r2 = g_rows[i + 2], r3 = g_rows[i + 3];
        float4 v0 = Sv[(size_t)r0 * 128 + q];
        float4 v1 = Sv[(size_t)r1 * 128 + q];
        float4 v2 = Sv[(size_t)r2 * 128 + q];
        float4 v3 = Sv[(size_t)r3 * 128 + q];
        acc.x += v0.x; acc.y += v0.y; acc.z += v0.z; acc.w += v0.w;
        acc.x += v1.x; acc.y += v1.y; acc.z += v1.z; acc.w += v1.w;
        acc.x += v2.x; acc.y += v2.y; acc.z += v2.z; acc.w += v2.w;
        acc.x += v3.x; acc.y += v3.y; acc.z += v3.z; acc.w += v3.w;
    }
    for (; i < s1; i++) {
        float4 v = Sv[(size_t)g_rows[i] * 128 + q];
        acc.x += v.x; acc.y += v.y; acc.z += v.z; acc.w += v.w;
    }
    reinterpret_cast<float4*>(g_part + (size_t)blockIdx.x * D)[q] = acc;
}

// ---------------- K4: reduce segment partials -> fp16 centroids ----------------
__global__ void k_conv() {
    int c = blockIdx.x, t = threadIdx.x;     // 64 blocks x 512 threads
    float s = 0.f;
#pragma unroll 8
    for (int seg = 0; seg < GSEG; seg++) s += g_part[(size_t)(c * GSEG + seg) * D + t];
    g_cent[c * D + t] = __float2half(s * g_scale[c]);
}

// ---------------- K5: staging + interleaved dual GEMM + weighted CE + finalize -------
// K-permuted fragments: within each 16-k chunk, lane t's virtual k {2t,2t+1,2t+8,2t+9}
// maps to physical k {4t,4t+1,4t+2,4t+3}. A and B both use this map (sum over k is
// order-invariant) -> A loads are LDG.128, B loads are single LDS.64.

__device__ __forceinline__ uint32_t h2(float x, float y) {
    __half2 h = __floats2half2_rn(x, y);
    return *reinterpret_cast<uint32_t*>(&h);
}

__device__ __forceinline__ void mma16816(float* c,
                                         uint32_t a0, uint32_t a1, uint32_t a2, uint32_t a3,
                                         uint32_t b0, uint32_t b1) {
    asm volatile(
        "mma.sync.aligned.m16n8k16.row.col.f32.f16.f16.f32 "
        "{%0,%1,%2,%3}, {%4,%5,%6,%7}, {%8,%9}, {%0,%1,%2,%3};\n"
        : "+f"(c[0]), "+f"(c[1]), "+f"(c[2]), "+f"(c[3])
        : "r"(a0), "r"(a1), "r"(a2), "r"(a3), "r"(b0), "r"(b1));
}

#define P2_THREADS 256
#define P2_BLOCKS 296
#define CENT_STRIDE_H 528     // halves per class row; 1056B = 264 words, 264%32==8 -> LDS.64 conflict-free
#define CENT_SMEM_BYTES (C * CENT_STRIDE_H * 2)

__global__ __launch_bounds__(P2_THREADS, 2)
void k_main(const float* __restrict__ S1, const float* __restrict__ S2,
            const int* __restrict__ labels,
            float* __restrict__ out, int n) {
    extern __shared__ __half cent_sh[];
    __shared__ float red[8][2];

    int tid = threadIdx.x;

    // Stage fp16 centroids into padded shared (uint4 = 8 halves per chunk)
    {
        const uint4* src = reinterpret_cast<const uint4*>(g_cent);
        for (int i = tid; i < C * D / 8; i += P2_THREADS) {
            int c = i >> 6;                 // 64 chunks per class row
            int x8 = i & 63;
            *reinterpret_cast<uint4*>(cent_sh + c * CENT_STRIDE_H + x8 * 8) = src[i];
        }
    }
    __syncthreads();

    int lane = tid & 31, wid = tid >> 5;
    int g = lane >> 2, t = lane & 3;
    int gwarp = blockIdx.x * (P2_THREADS / 32) + wid;
    int nwarps = gridDim.x * (P2_THREADS / 32);
    int ntiles = n >> 4;

    float lsum0 = 0.f, lsum1 = 0.f;

    for (int tile = gwarp; tile < ntiles; tile += nwarps) {
        int rb = tile << 4;

        const float* a1r1 = S1 + (size_t)(rb + g) * D;
        const float* a1r2 = a1r1 + 8 * D;
        const float* a2r1 = S2 + (size_t)(rb + g) * D;
        const float* a2r2 = a2r1 + 8 * D;

        float acc[2][8][4];
#pragma unroll
        for (int m = 0; m < 2; m++)
#pragma unroll
            for (int nt = 0; nt < 8; nt++)
#pragma unroll
                for (int j = 0; j < 4; j++) acc[m][nt][j] = 0.f;

#pragma unroll 2
        for (int kt = 0; kt < D / 16; kt++) {
            int ko = kt * 16 + 4 * t;       // physical float offset for this lane
            float4 x1a = *reinterpret_cast<const float4*>(a1r1 + ko);
            float4 x1b = *reinterpret_cast<const float4*>(a1r2 + ko);
            float4 x2a = *reinterpret_cast<const float4*>(a2r1 + ko);
            float4 x2b = *reinterpret_cast<const float4*>(a2r2 + ko);
            uint32_t a0m0 = h2(x1a.x, x1a.y), a2m0 = h2(x1a.z, x1a.w);
            uint32_t a1m0 = h2(x1b.x, x1b.y), a3m0 = h2(x1b.z, x1b.w);
            uint32_t a0m1 = h2(x2a.x, x2a.y), a2m1 = h2(x2a.z, x2a.w);
            uint32_t a1m1 = h2(x2b.x, x2b.y), a3m1 = h2(x2b.z, x2b.w);
#pragma unroll
            for (int nt = 0; nt < 8; nt++) {
                uint2 b = *reinterpret_cast<const uint2*>(
                    cent_sh + (nt * 8 + g) * CENT_STRIDE_H + ko);
                mma16816(acc[0][nt], a0m0, a1m0, a2m0, a3m0, b.x, b.y);
                mma16816(acc[1][nt], a0m1, a1m1, a2m1, a3m1, b.x, b.y);
            }
        }

        // post-loop: labels + precomputed weights (short live ranges)
        int lab0 = labels[rb + g];
        int lab1 = labels[rb + 8 + g];
        float w0 = g_w[rb + g];
        float w1 = g_w[rb + 8 + g];

#pragma unroll
        for (int m = 0; m < 2; m++) {
#pragma unroll
            for (int j = 0; j < 2; j++) {
                int lab = j ? lab1 : lab0;
                float w = j ? w1 : w0;
                float mx = -1e30f;
#pragma unroll
                for (int nt = 0; nt < 8; nt++) {
                    mx = fmaxf(mx, acc[m][nt][2 * j]);
                    mx = fmaxf(mx, acc[m][nt][2 * j + 1]);
                }
                mx = fmaxf(mx, __shfl_xor_sync(0xffffffffu, mx, 1));
                mx = fmaxf(mx, __shfl_xor_sync(0xffffffffu, mx, 2));
                float s = 0.f;
#pragma unroll
                for (int nt = 0; nt < 8; nt++) {
                    s += __expf(acc[m][nt][2 * j] - mx);
                    s += __expf(acc[m][nt][2 * j + 1] - mx);
                }
                s += __shfl_xor_sync(0xffffffffu, s, 1);
                s += __shfl_xor_sync(0xffffffffu, s, 2);
                float lse = mx + __logf(s);
                int nt_l = lab >> 3;
                int t_l = (lab >> 1) & 3;
                float sel = 0.f;
#pragma unroll
                for (int nt = 0; nt < 8; nt++) {
                    float v = (lab & 1) ? acc[m][nt][2 * j + 1] : acc[m][nt][2 * j];
                    sel += ((nt == nt_l) && (t == t_l)) ? v : 0.f;
                }
                sel += __shfl_xor_sync(0xffffffffu, sel, 1);
                sel += __shfl_xor_sync(0xffffffffu, sel, 2);
                float ce = (lse - sel) * w;   // quad-uniform
                if (m == 0) lsum0 += ce;
                else        lsum1 += ce;
            }
        }
    }

    // CE accumulated on all 4 quad lanes -> scale by 1/4
    lsum0 *= 0.25f;
    lsum1 *= 0.25f;
#pragma unroll
    for (int off = 16; off > 0; off >>= 1) {
        lsum0 += __shfl_down_sync(0xffffffffu, lsum0, off);
        lsum1 += __shfl_down_sync(0xffffffffu, lsum1, off);
    }
    if (lane == 0) { red[wid][0] = lsum0; red[wid][1] = lsum1; }
    __syncthreads();
    if (tid == 0) {
        float s0 = 0.f, s1 = 0.f;
#pragma unroll
        for (int wq = 0; wq < P2_THREADS / 32; wq++) { s0 += red[wq][0]; s1 += red[wq][1]; }
        atomicAdd(&g_loss[0], s0);
        atomicAdd(&g_loss[1], s1);
        __threadfence();
        int ticket = atomicAdd(&g_done, 1);
        if (ticket == gridDim.x - 1) {
            float L = g_loss[0] / (float)n;
            float G = g_loss[1] / (float)n;
            out[0] = 0.5f * ((1.f - GLW) * L + GLW * G);
            atomicExch(&g_done, 0);   // reset for next graph replay
        }
    }
}

// ---------------- launch ----------------
extern "C" void kernel_launch(void* const* d_in, const int* in_sizes, int n_in,
                              void* d_out, int out_size) {
    const float* S1 = (const float*)d_in[0];
    const float* S2 = (const float*)d_in[1];
    const int* seg = (const int*)d_in[2];
    const float* sim = (const float*)d_in[3];
    int n = in_sizes[2];  // N = 65536

    cudaFuncSetAttribute(k_main, cudaFuncAttributeMaxDynamicSharedMemorySize,
                         CENT_SMEM_BYTES);

    k_pre<<<NHB, 256>>>(seg, sim, n);
    k_scan<<<1, C>>>();
    k_scatter<<<NHB, 256>>>(seg, n);
    k_gather<<<C * GSEG, 128>>>(S1);
    k_conv<<<C, 512>>>();
    k_main<<<P2_BLOCKS, P2_THREADS, CENT_SMEM_BYTES>>>(S1, S2, seg, (float*)d_out, n);
}